// round 3
// baseline (speedup 1.0000x reference)
#include <cuda_runtime.h>

#define B_SZ 512
#define D_SZ 1024
#define P_SZ 16
#define N_SZ 128
#define ALPHA_F 0.8f
#define NROWS 145            // row 0 = tgt, 1..16 = rel, 17..144 = irr
#define SPLIT 2
#define NBLOCKS (B_SZ * SPLIT)   // 1024
#define TPB 256

__device__ float g_pos[NBLOCKS];
__device__ float g_neg[NBLOCKS];
__device__ float g_diag[B_SZ];
__device__ unsigned int g_count = 0;

__global__ void __launch_bounds__(TPB, 4)
contrastive_loss_kernel(const float* __restrict__ src,
                        const float* __restrict__ tgt,
                        const float* __restrict__ rel,
                        const float* __restrict__ irr,
                        float* __restrict__ out)
{
    __shared__ float s_src[D_SZ];
    __shared__ float s_red[8];
    __shared__ float s_pos[8];
    __shared__ float s_neg[8];
    __shared__ float s_inv;
    __shared__ int   s_last;

    const int blk  = blockIdx.x;
    const int b    = blk >> 1;          // batch row
    const int s    = blk & 1;           // split index
    const int tid  = threadIdx.x;
    const int wid  = tid >> 5;
    const int lane = tid & 31;

    // ---- load src row into shared (one float4 per thread); sum of squares ----
    const float4* srcv = reinterpret_cast<const float4*>(src + (size_t)b * D_SZ);
    float4 v0 = srcv[tid];
    reinterpret_cast<float4*>(s_src)[tid] = v0;
    float ss = v0.x * v0.x + v0.y * v0.y + v0.z * v0.z + v0.w * v0.w;
    #pragma unroll
    for (int o = 16; o > 0; o >>= 1) ss += __shfl_xor_sync(0xFFFFFFFFu, ss, o);
    if (lane == 0) s_red[wid] = ss;
    __syncthreads();
    if (tid == 0) {
        float t = 0.f;
        #pragma unroll
        for (int i = 0; i < 8; i++) t += s_red[i];
        s_inv = rsqrtf(fmaxf(t, 1e-24f));          // 1/max(||src||,1e-12)
    }
    __syncthreads();
    const float inv_src = s_inv;

    // ---- this block's slice of the 145 rows ----
    const int r0 = (s * NROWS) / SPLIT;            // 0 or 72
    const int r1 = ((s + 1) * NROWS) / SPLIT;      // 72 or 145

    float pos_acc = 0.f, neg_acc = 0.f;
    float diag = 0.f;

    for (int r = r0 + wid; r < r1; r += 8) {
        const float* row;
        if (r == 0)
            row = tgt + (size_t)b * D_SZ;
        else if (r <= P_SZ)
            row = rel + ((size_t)b * P_SZ + (r - 1)) * D_SZ;
        else
            row = irr + ((size_t)b * N_SZ + (r - 1 - P_SZ)) * D_SZ;

        const float4* rv = reinterpret_cast<const float4*>(row);
        float dot = 0.f, rss = 0.f;
        #pragma unroll
        for (int j = 0; j < 8; j++) {              // 8 LDG.128 batched in flight
            int idx = j * 32 + lane;
            float4 v  = rv[idx];
            float4 sv = reinterpret_cast<const float4*>(s_src)[idx];
            dot += v.x * sv.x + v.y * sv.y + v.z * sv.z + v.w * sv.w;
            rss += v.x * v.x + v.y * v.y + v.z * v.z + v.w * v.w;
        }
        #pragma unroll
        for (int o = 16; o > 0; o >>= 1) {
            dot += __shfl_xor_sync(0xFFFFFFFFu, dot, o);
            rss += __shfl_xor_sync(0xFFFFFFFFu, rss, o);
        }
        if (lane == 0) {
            float c = dot * inv_src * rsqrtf(fmaxf(rss, 1e-24f));
            if (r == 0)            diag = c;
            else if (r <= P_SZ)    pos_acc += expf(c);
            else                   neg_acc += expf(c);
        }
    }

    if (lane == 0) { s_pos[wid] = pos_acc; s_neg[wid] = neg_acc; }
    __syncthreads();

    if (tid == 0) {
        float ps = 0.f, ns = 0.f;
        #pragma unroll
        for (int i = 0; i < 8; i++) { ps += s_pos[i]; ns += s_neg[i]; }
        g_pos[blk] = ps;
        g_neg[blk] = ns;
        if (s == 0) g_diag[b] = diag;   // tid 0 == warp 0 lane 0 handled r==0

        // release-ordered arrival: orders this thread's prior global stores;
        // no threadfence -> no CCTL.IVALL L1 flush
        unsigned int old;
        asm volatile("atom.acq_rel.gpu.global.add.u32 %0, [%1], %2;"
                     : "=r"(old)
                     : "l"(&g_count), "r"(1u)
                     : "memory");
        s_last = (old == NBLOCKS - 1);
    }
    __syncthreads();

    // ---- last block computes the final loss (fused reduction) ----
    if (s_last) {
        float acc = 0.f;
        #pragma unroll
        for (int it = 0; it < B_SZ / TPB; it++) {
            int bb = it * TPB + tid;
            float ps = g_pos[bb * SPLIT] + g_pos[bb * SPLIT + 1];
            float ns = g_neg[bb * SPLIT] + g_neg[bb * SPLIT + 1];
            float pos_score = 1.f + ps;
            float lp = logf(pos_score);
            float ln = logf(pos_score + ns);
            acc += -(ALPHA_F * g_diag[bb] + (1.f - ALPHA_F) * (lp - ln));
        }
        #pragma unroll
        for (int o = 16; o > 0; o >>= 1) acc += __shfl_xor_sync(0xFFFFFFFFu, acc, o);
        if (lane == 0) s_red[wid] = acc;
        __syncthreads();
        if (tid == 0) {
            float t = 0.f;
            #pragma unroll
            for (int i = 0; i < 8; i++) t += s_red[i];
            out[0] = t * (1.0f / (float)B_SZ);
            g_count = 0;                // reset for the next graph replay
        }
    }
}

extern "C" void kernel_launch(void* const* d_in, const int* in_sizes, int n_in,
                              void* d_out, int out_size)
{
    const float* src = (const float*)d_in[0];   // [B, D]
    const float* tgt = (const float*)d_in[1];   // [B, D]
    const float* rel = (const float*)d_in[2];   // [B, P, D]
    const float* irr = (const float*)d_in[3];   // [B, N, D]
    float* out = (float*)d_out;

    contrastive_loss_kernel<<<NBLOCKS, TPB>>>(src, tgt, rel, irr, out);
}

// round 4
// speedup vs baseline: 1.0367x; 1.0367x over previous
#include <cuda_runtime.h>

#define B_SZ 512
#define D_SZ 1024
#define P_SZ 16
#define N_SZ 128
#define ALPHA_F 0.8f
#define NROWS 145                 // row 0 = tgt, 1..16 = rel, 17..144 = irr
#define SPLIT 8
#define NBLOCKS (B_SZ * SPLIT)    // 4096
#define TPB 128

__device__ float g_pos[NBLOCKS];
__device__ float g_neg[NBLOCKS];
__device__ float g_diag[B_SZ];
__device__ unsigned int g_count = 0;

__device__ __forceinline__ const float4*
row_ptr(const float* __restrict__ tgt, const float* __restrict__ rel,
        const float* __restrict__ irr, int b, int r)
{
    const float* p;
    if (r == 0)
        p = tgt + (size_t)b * D_SZ;
    else if (r <= P_SZ)
        p = rel + ((size_t)b * P_SZ + (r - 1)) * D_SZ;
    else
        p = irr + ((size_t)b * N_SZ + (r - 1 - P_SZ)) * D_SZ;
    return reinterpret_cast<const float4*>(p);
}

__global__ void __launch_bounds__(TPB, 8)
contrastive_loss_kernel(const float* __restrict__ src,
                        const float* __restrict__ tgt,
                        const float* __restrict__ rel,
                        const float* __restrict__ irr,
                        float* __restrict__ out)
{
    __shared__ float4 s_srcv[D_SZ / 4];
    __shared__ float  s_red[4];
    __shared__ float  s_pos[4];
    __shared__ float  s_neg[4];
    __shared__ float  s_inv;
    __shared__ int    s_last;

    const int blk  = blockIdx.x;
    const int b    = blk >> 3;            // batch row
    const int s    = blk & 7;             // split index
    const int tid  = threadIdx.x;
    const int wid  = tid >> 5;
    const int lane = tid & 31;

    // ---- prologue: src row -> smem, sum of squares ----
    const float4* srcv = reinterpret_cast<const float4*>(src + (size_t)b * D_SZ);
    float ss = 0.f;
    #pragma unroll
    for (int i = 0; i < 2; i++) {
        int idx = i * TPB + tid;
        float4 v = srcv[idx];
        s_srcv[idx] = v;
        ss += v.x * v.x + v.y * v.y + v.z * v.z + v.w * v.w;
    }
    #pragma unroll
    for (int o = 16; o > 0; o >>= 1) ss += __shfl_xor_sync(0xFFFFFFFFu, ss, o);
    if (lane == 0) s_red[wid] = ss;
    __syncthreads();
    if (tid == 0)
        s_inv = rsqrtf(fmaxf(s_red[0] + s_red[1] + s_red[2] + s_red[3], 1e-24f));
    __syncthreads();
    const float inv_src = s_inv;

    // ---- this block's slice of the 145 rows ----
    const int r0 = (s * NROWS) / SPLIT;
    const int r1 = ((s + 1) * NROWS) / SPLIT;

    float pos_acc = 0.f, neg_acc = 0.f, diag = 0.f;

    // pairs of rows per warp iteration: shared LDS stream, interleaved reductions
    for (int base = r0 + wid * 2; base < r1; base += 8) {
        const int rA = base;
        const int rB = base + 1;
        const bool hasB = (rB < r1);

        const float4* pA = row_ptr(tgt, rel, irr, b, rA);
        const float4* pB = hasB ? row_ptr(tgt, rel, irr, b, rB) : pA;

        float dotA = 0.f, rssA = 0.f, dotB = 0.f, rssB = 0.f;
        #pragma unroll
        for (int h = 0; h < 2; h++) {
            float4 va[4], vb[4];
            #pragma unroll
            for (int j = 0; j < 4; j++) {           // 8 LDG.128 batched in flight
                int idx = h * 128 + j * 32 + lane;
                va[j] = __ldcs(&pA[idx]);
                vb[j] = __ldcs(&pB[idx]);
            }
            #pragma unroll
            for (int j = 0; j < 4; j++) {
                int idx = h * 128 + j * 32 + lane;
                float4 sv = s_srcv[idx];
                dotA += va[j].x * sv.x + va[j].y * sv.y + va[j].z * sv.z + va[j].w * sv.w;
                rssA += va[j].x * va[j].x + va[j].y * va[j].y + va[j].z * va[j].z + va[j].w * va[j].w;
                dotB += vb[j].x * sv.x + vb[j].y * sv.y + vb[j].z * sv.z + vb[j].w * sv.w;
                rssB += vb[j].x * vb[j].x + vb[j].y * vb[j].y + vb[j].z * vb[j].z + vb[j].w * vb[j].w;
            }
        }
        // four interleaved butterfly chains: latency overlapped
        #pragma unroll
        for (int o = 16; o > 0; o >>= 1) {
            dotA += __shfl_xor_sync(0xFFFFFFFFu, dotA, o);
            rssA += __shfl_xor_sync(0xFFFFFFFFu, rssA, o);
            dotB += __shfl_xor_sync(0xFFFFFFFFu, dotB, o);
            rssB += __shfl_xor_sync(0xFFFFFFFFu, rssB, o);
        }
        if (lane == 0) {
            float cA = dotA * inv_src * rsqrtf(fmaxf(rssA, 1e-24f));
            if (rA == 0)            diag = cA;
            else if (rA <= P_SZ)    pos_acc += expf(cA);
            else                    neg_acc += expf(cA);
            if (hasB) {
                float cB = dotB * inv_src * rsqrtf(fmaxf(rssB, 1e-24f));
                if (rB <= P_SZ)     pos_acc += expf(cB);    // rB >= 1 always
                else                neg_acc += expf(cB);
            }
        }
    }

    if (lane == 0) { s_pos[wid] = pos_acc; s_neg[wid] = neg_acc; }
    __syncthreads();

    if (tid == 0) {
        g_pos[blk] = s_pos[0] + s_pos[1] + s_pos[2] + s_pos[3];
        g_neg[blk] = s_neg[0] + s_neg[1] + s_neg[2] + s_neg[3];
        if (s == 0) g_diag[b] = diag;   // tid0 = warp0 lane0 handled row 0

        unsigned int old;
        asm volatile("atom.acq_rel.gpu.global.add.u32 %0, [%1], %2;"
                     : "=r"(old)
                     : "l"(&g_count), "r"(1u)
                     : "memory");
        s_last = (old == NBLOCKS - 1);
    }
    __syncthreads();

    // ---- last block computes the final loss ----
    if (s_last) {
        float acc = 0.f;
        #pragma unroll
        for (int it = 0; it < B_SZ / TPB; it++) {
            int bb = it * TPB + tid;
            float ps = 0.f, ns = 0.f;
            #pragma unroll
            for (int k = 0; k < SPLIT; k++) {
                ps += g_pos[bb * SPLIT + k];
                ns += g_neg[bb * SPLIT + k];
            }
            float pos_score = 1.f + ps;
            float lp = logf(pos_score);
            float ln = logf(pos_score + ns);
            acc += -(ALPHA_F * g_diag[bb] + (1.f - ALPHA_F) * (lp - ln));
        }
        #pragma unroll
        for (int o = 16; o > 0; o >>= 1) acc += __shfl_xor_sync(0xFFFFFFFFu, acc, o);
        if (lane == 0) s_red[wid] = acc;
        __syncthreads();
        if (tid == 0) {
            out[0] = (s_red[0] + s_red[1] + s_red[2] + s_red[3]) * (1.0f / (float)B_SZ);
            g_count = 0;                // reset for next graph replay
        }
    }
}

extern "C" void kernel_launch(void* const* d_in, const int* in_sizes, int n_in,
                              void* d_out, int out_size)
{
    const float* src = (const float*)d_in[0];   // [B, D]
    const float* tgt = (const float*)d_in[1];   // [B, D]
    const float* rel = (const float*)d_in[2];   // [B, P, D]
    const float* irr = (const float*)d_in[3];   // [B, N, D]
    float* out = (float*)d_out;

    contrastive_loss_kernel<<<NBLOCKS, TPB>>>(src, tgt, rel, irr, out);
}